// round 14
// baseline (speedup 1.0000x reference)
#include <cuda_runtime.h>
#include <cuda_bf16.h>
#include <math.h>

#define Nn   12288
#define Ee   393216
#define INF  256
#define Hh   128
#define DZv  64
#define NB   (Nn / 128)            // 96 tile-rows
#define NBLK (NB * (NB + 1) / 2)   // 4656 triangular tiles

// ---------------- scratch (device globals; NEVER passed as kernel args) -----
__device__ __align__(16) int   g_degi[Nn];
__device__ __align__(16) int   g_off[Nn];
__device__ __align__(16) int   g_pos[Nn];
__device__ __align__(16) int   g_csr[Ee];
__device__ __align__(16) float g_t0[Nn * Hh];
__device__ __align__(16) float g_hid[Nn * Hh];
__device__ __align__(16) float g_t1[Nn * DZv];
__device__ __align__(16) float g_t2[Nn * DZv];
__device__ __align__(16) __nv_bfloat16 g_Za[Nn * 192];  // [hi | lo | hi]
__device__ __align__(16) __nv_bfloat16 g_Zb[Nn * 192];  // [hi | hi | lo]
__device__ __align__(16) int   g_src[Ee];
__device__ __align__(16) int   g_dst[Ee];

__device__ __forceinline__ float node_norm(int node) {
    return rsqrtf(fmaxf((float)g_degi[node], 1.0f));
}

// ---------------- zero (before cvt: degree atomics live in k_cvt now) --------
__global__ void k_zero() {
    int i = blockIdx.x * blockDim.x + threadIdx.x;
    if (i < Nn) { g_degi[i] = 0; g_pos[i] = 0; }
}

// ---------------- edge index conversion + degree (fused) ---------------------
__global__ void k_cvt_idx(const int* __restrict__ ei) {
    __shared__ int s_is64;
    if (threadIdx.x == 0) {
        int is64 = 1;
        for (int i = 0; i < 32; ++i)
            if (ei[2 * i + 1] != 0) { is64 = 0; break; }
        s_is64 = is64;
    }
    __syncthreads();
    int e = blockIdx.x * blockDim.x + threadIdx.x;
    if (e >= Ee) return;
    int s, d;
    if (s_is64) {
        s = ei[2 * e];
        d = ei[2 * (Ee + e)];
    } else {
        s = ei[e];
        d = ei[Ee + e];
    }
    g_src[e] = s;
    g_dst[e] = d;
    atomicAdd(&g_degi[d], 1);
}

// ---------------- exclusive prefix scan of g_degi -> g_off (1 block, 1024) ---
__global__ void k_scan() {
    const int PER = Nn / 1024;
    int tid = threadIdx.x;
    int lane = tid & 31, wid = tid >> 5;
    int base = tid * PER;
    int loc[PER];
    int sum = 0;
#pragma unroll
    for (int i = 0; i < PER; ++i) { loc[i] = sum; sum += g_degi[base + i]; }
    int v = sum;
#pragma unroll
    for (int off = 1; off < 32; off <<= 1) {
        int nb = __shfl_up_sync(0xffffffffu, v, off);
        if (lane >= off) v += nb;
    }
    __shared__ int ws[32];
    if (lane == 31) ws[wid] = v;
    __syncthreads();
    if (wid == 0) {
        int w = ws[lane];
#pragma unroll
        for (int off = 1; off < 32; off <<= 1) {
            int nb = __shfl_up_sync(0xffffffffu, w, off);
            if (lane >= off) w += nb;
        }
        ws[lane] = w;
    }
    __syncthreads();
    int warp_excl = (wid > 0) ? ws[wid - 1] : 0;
    int thr_excl = warp_excl + v - sum;
#pragma unroll
    for (int i = 0; i < PER; ++i) g_off[base + i] = thr_excl + loc[i];
}

__global__ void k_fill() {
    int e = blockIdx.x * blockDim.x + threadIdx.x;
    if (e >= Ee) return;
    int d = g_dst[e];
    int p = g_off[d] + atomicAdd(&g_pos[d], 1);
    g_csr[p] = g_src[e];
}

// ---------------- t0 = (features @ W0) * norm  [tiled SGEMM] -----------------
__global__ void k_gemm_t0(const float* __restrict__ A, const float* __restrict__ B) {
    __shared__ float As[16][68];
    __shared__ float Bs[16][68];
    int tid = threadIdx.x;
    int tx = tid & 15, ty = tid >> 4;
    int r0 = blockIdx.y * 64, c0 = blockIdx.x * 64;

    float acc[4][4] = {};
    for (int k0 = 0; k0 < INF; k0 += 16) {
        {
            int row = tid >> 2;
            int kk  = (tid & 3) * 4;
            float4 v = *(const float4*)&A[(size_t)(r0 + row) * INF + k0 + kk];
            As[kk + 0][row] = v.x; As[kk + 1][row] = v.y;
            As[kk + 2][row] = v.z; As[kk + 3][row] = v.w;
        }
        {
            int krow = tid >> 4;
            int col  = (tid & 15) * 4;
            float4 w = *(const float4*)&B[(size_t)(k0 + krow) * Hh + c0 + col];
            *(float4*)&Bs[krow][col] = w;
        }
        __syncthreads();
#pragma unroll
        for (int k = 0; k < 16; ++k) {
            float4 a = *(float4*)&As[k][ty * 4];
            float4 b = *(float4*)&Bs[k][tx * 4];
            float av[4] = {a.x, a.y, a.z, a.w};
            float bv[4] = {b.x, b.y, b.z, b.w};
#pragma unroll
            for (int i = 0; i < 4; ++i)
#pragma unroll
                for (int j = 0; j < 4; ++j)
                    acc[i][j] += av[i] * bv[j];
        }
        __syncthreads();
    }
#pragma unroll
    for (int i = 0; i < 4; ++i) {
        int r = r0 + ty * 4 + i;
        float n = node_norm(r);
        float4 o = make_float4(acc[i][0] * n, acc[i][1] * n, acc[i][2] * n, acc[i][3] * n);
        *(float4*)&g_t0[(size_t)r * Hh + c0 + tx * 4] = o;
    }
}

// ---------------- merged t1/t2 = norm^2 * (hid @ {Wm,Ws}) --------------------
__global__ void k_gemm_ms(const float* __restrict__ B1, const float* __restrict__ B2) {
    __shared__ float As[16][68];
    __shared__ float Bs1[16][68];
    __shared__ float Bs2[16][68];
    int tid = threadIdx.x;
    int tx = tid & 15, ty = tid >> 4;
    int r0 = blockIdx.x * 64;

    float acc1[4][4] = {};
    float acc2[4][4] = {};
    for (int k0 = 0; k0 < Hh; k0 += 16) {
        {
            int row = tid >> 2;
            int kk  = (tid & 3) * 4;
            float4 v = *(const float4*)&g_hid[(size_t)(r0 + row) * Hh + k0 + kk];
            As[kk + 0][row] = v.x; As[kk + 1][row] = v.y;
            As[kk + 2][row] = v.z; As[kk + 3][row] = v.w;
        }
        {
            int krow = tid >> 4;
            int col  = (tid & 15) * 4;
            float4 w1 = *(const float4*)&B1[(size_t)(k0 + krow) * DZv + col];
            *(float4*)&Bs1[krow][col] = w1;
            float4 w2 = *(const float4*)&B2[(size_t)(k0 + krow) * DZv + col];
            *(float4*)&Bs2[krow][col] = w2;
        }
        __syncthreads();
#pragma unroll
        for (int k = 0; k < 16; ++k) {
            float4 a = *(float4*)&As[k][ty * 4];
            float av[4] = {a.x, a.y, a.z, a.w};
            float4 b1 = *(float4*)&Bs1[k][tx * 4];
            float bv1[4] = {b1.x, b1.y, b1.z, b1.w};
            float4 b2 = *(float4*)&Bs2[k][tx * 4];
            float bv2[4] = {b2.x, b2.y, b2.z, b2.w};
#pragma unroll
            for (int i = 0; i < 4; ++i)
#pragma unroll
                for (int j = 0; j < 4; ++j) {
                    acc1[i][j] += av[i] * bv1[j];
                    acc2[i][j] += av[i] * bv2[j];
                }
        }
        __syncthreads();
    }
#pragma unroll
    for (int i = 0; i < 4; ++i) {
        int r = r0 + ty * 4 + i;
        float n = node_norm(r);
        float s = n * n;
        float4 o1 = make_float4(acc1[i][0] * s, acc1[i][1] * s, acc1[i][2] * s, acc1[i][3] * s);
        *(float4*)&g_t1[(size_t)r * DZv + tx * 4] = o1;
        float4 o2 = make_float4(acc2[i][0] * s, acc2[i][1] * s, acc2[i][2] * s, acc2[i][3] * s);
        *(float4*)&g_t2[(size_t)r * DZv + tx * 4] = o2;
    }
}

// ---------------- gather-aggregate hid (warp/node, unroll x4 for MLP) --------
__global__ void k_agg_h() {
    int gtid = blockIdx.x * blockDim.x + threadIdx.x;
    int node = gtid >> 5;
    int lane = gtid & 31;
    if (node >= Nn) return;
    int beg = g_off[node];
    int end = beg + g_degi[node];
    float4 a0 = make_float4(0.f, 0.f, 0.f, 0.f);
    float4 a1 = make_float4(0.f, 0.f, 0.f, 0.f);
    float4 a2 = make_float4(0.f, 0.f, 0.f, 0.f);
    float4 a3 = make_float4(0.f, 0.f, 0.f, 0.f);
    int i = beg;
    for (; i + 3 < end; i += 4) {
        int s0 = g_csr[i], s1 = g_csr[i + 1], s2 = g_csr[i + 2], s3 = g_csr[i + 3];
        float4 v0 = ((const float4*)&g_t0[(size_t)s0 * Hh])[lane];
        float4 v1 = ((const float4*)&g_t0[(size_t)s1 * Hh])[lane];
        float4 v2 = ((const float4*)&g_t0[(size_t)s2 * Hh])[lane];
        float4 v3 = ((const float4*)&g_t0[(size_t)s3 * Hh])[lane];
        a0.x += v0.x; a0.y += v0.y; a0.z += v0.z; a0.w += v0.w;
        a1.x += v1.x; a1.y += v1.y; a1.z += v1.z; a1.w += v1.w;
        a2.x += v2.x; a2.y += v2.y; a2.z += v2.z; a2.w += v2.w;
        a3.x += v3.x; a3.y += v3.y; a3.z += v3.z; a3.w += v3.w;
    }
    for (; i < end; ++i) {
        int s = g_csr[i];
        float4 v = ((const float4*)&g_t0[(size_t)s * Hh])[lane];
        a0.x += v.x; a0.y += v.y; a0.z += v.z; a0.w += v.w;
    }
    float4 acc = make_float4(a0.x + a1.x + a2.x + a3.x,
                             a0.y + a1.y + a2.y + a3.y,
                             a0.z + a1.z + a2.z + a3.z,
                             a0.w + a1.w + a2.w + a3.w);
    ((float4*)&g_hid[(size_t)node * Hh])[lane] = acc;
}

// ---------------- fused gather(m,s) + Z + bf16 split (warp/node) -------------
// lanes 0-15 gather t1 chunks, 16-31 gather t2; shfl_xor(16) exchanges m<->s;
// lanes 0-15 compute z for their 4 cols and write Za/Zb directly.
__global__ void k_agg_msz(const float* __restrict__ noise) {
    int gtid = blockIdx.x * blockDim.x + threadIdx.x;
    int node = gtid >> 5;
    int lane = gtid & 31;
    if (node >= Nn) return;
    int beg = g_off[node];
    int end = beg + g_degi[node];
    const float* T = (lane < 16) ? g_t1 : g_t2;
    int q = lane & 15;

    float4 a0 = make_float4(0.f, 0.f, 0.f, 0.f);
    float4 a1 = make_float4(0.f, 0.f, 0.f, 0.f);
    int i = beg;
    for (; i + 1 < end; i += 2) {
        int s0 = g_csr[i], s1 = g_csr[i + 1];
        float4 v0 = ((const float4*)&T[(size_t)s0 * DZv])[q];
        float4 v1 = ((const float4*)&T[(size_t)s1 * DZv])[q];
        a0.x += v0.x; a0.y += v0.y; a0.z += v0.z; a0.w += v0.w;
        a1.x += v1.x; a1.y += v1.y; a1.z += v1.z; a1.w += v1.w;
    }
    for (; i < end; ++i) {
        int s = g_csr[i];
        float4 v = ((const float4*)&T[(size_t)s * DZv])[q];
        a0.x += v.x; a0.y += v.y; a0.z += v.z; a0.w += v.w;
    }
    float n = node_norm(node);
    float4 sc;
    sc.x = fmaxf((a0.x + a1.x) * n, 0.f);
    sc.y = fmaxf((a0.y + a1.y) * n, 0.f);
    sc.z = fmaxf((a0.z + a1.z) * n, 0.f);
    sc.w = fmaxf((a0.w + a1.w) * n, 0.f);

    // exchange with partner lane (^16): lanes<16 receive s-values
    float4 other;
    other.x = __shfl_xor_sync(0xffffffffu, sc.x, 16);
    other.y = __shfl_xor_sync(0xffffffffu, sc.y, 16);
    other.z = __shfl_xor_sync(0xffffffffu, sc.z, 16);
    other.w = __shfl_xor_sync(0xffffffffu, sc.w, 16);

    if (lane < 16) {
        float4 m4 = sc, s4 = other;
        float4 nz = ((const float4*)&noise[(size_t)node * DZv])[q];
        float z[4];
        z[0] = nz.x * expf(s4.x) + m4.x;
        z[1] = nz.y * expf(s4.y) + m4.y;
        z[2] = nz.z * expf(s4.z) + m4.z;
        z[3] = nz.w * expf(s4.w) + m4.w;
        __nv_bfloat16 hi[4], lo[4];
#pragma unroll
        for (int t = 0; t < 4; ++t) {
            hi[t] = __float2bfloat16(z[t]);
            lo[t] = __float2bfloat16(z[t] - __bfloat162float(hi[t]));
        }
        __nv_bfloat162 h01, h23, l01, l23;
        h01.x = hi[0]; h01.y = hi[1]; h23.x = hi[2]; h23.y = hi[3];
        l01.x = lo[0]; l01.y = lo[1]; l23.x = lo[2]; l23.y = lo[3];
        size_t base2 = (size_t)node * 96 + q * 2;   // index in bf162 units (192 bf16 = 96 pairs)
        __nv_bfloat162* Za2 = (__nv_bfloat162*)g_Za;
        __nv_bfloat162* Zb2 = (__nv_bfloat162*)g_Zb;
        // Za = [hi | lo | hi]
        Za2[base2 + 0]      = h01; Za2[base2 + 1]      = h23;
        Za2[base2 + 32]     = l01; Za2[base2 + 33]     = l23;
        Za2[base2 + 64]     = h01; Za2[base2 + 65]     = h23;
        // Zb = [hi | hi | lo]
        Zb2[base2 + 0]      = h01; Zb2[base2 + 1]      = h23;
        Zb2[base2 + 32]     = h01; Zb2[base2 + 33]     = h23;
        Zb2[base2 + 64]     = l01; Zb2[base2 + 65]     = l23;
    }
}

// ---------------- symmetric ZZ^T: triangular tiles + smem transpose ----------
#define ZPAD 8
#define ZLD  (64 + ZPAD)

union ZSmem {
    struct { __nv_bfloat16 A[128][ZLD]; __nv_bfloat16 B[128][ZLD]; } ab;
    float tr[128][33];
};

__device__ __forceinline__ unsigned smem_u32(const void* p) {
    return (unsigned)__cvta_generic_to_shared(p);
}

__global__ void __launch_bounds__(256, 2) k_zzt_sym(float* __restrict__ out) {
    __shared__ __align__(16) ZSmem sm;

    int tid  = threadIdx.x;
    int lane = tid & 31;
    int w    = tid >> 5;
    int wm   = w & 1;
    int wn   = w >> 1;

    int b = blockIdx.x;
    int by = (int)((sqrtf(8.0f * (float)b + 1.0f) - 1.0f) * 0.5f);
    while ((by + 1) * (by + 2) / 2 <= b) ++by;
    while (by * (by + 1) / 2 > b) --by;
    int bx = b - by * (by + 1) / 2;
    int r0 = by * 128;
    int c0 = bx * 128;

    float acc[4][4][4];
#pragma unroll
    for (int i = 0; i < 4; ++i)
#pragma unroll
        for (int j = 0; j < 4; ++j)
#pragma unroll
            for (int q = 0; q < 4; ++q) acc[i][j][q] = 0.f;

    for (int kc = 0; kc < 3; ++kc) {
#pragma unroll
        for (int it = 0; it < 4; ++it) {
            int quad = tid + it * 256;
            int row = quad >> 3;
            int q   = quad & 7;
            const uint4* ga = (const uint4*)&g_Za[(size_t)(r0 + row) * 192 + kc * 64];
            *(uint4*)&sm.ab.A[row][q * 8] = ga[q];
            const uint4* gb = (const uint4*)&g_Zb[(size_t)(c0 + row) * 192 + kc * 64];
            *(uint4*)&sm.ab.B[row][q * 8] = gb[q];
        }
        __syncthreads();

#pragma unroll
        for (int ks = 0; ks < 4; ++ks) {
            int k0 = ks * 16;
            unsigned a[4][4];
#pragma unroll
            for (int i = 0; i < 4; ++i) {
                int m0 = wm * 64 + i * 16;
                unsigned addr = smem_u32(&sm.ab.A[m0 + (lane & 15)][k0 + (lane >> 4) * 8]);
                asm volatile("ldmatrix.sync.aligned.m8n8.x4.shared.b16 {%0,%1,%2,%3}, [%4];"
                             : "=r"(a[i][0]), "=r"(a[i][1]), "=r"(a[i][2]), "=r"(a[i][3])
                             : "r"(addr));
            }
            unsigned bb[4][2];
#pragma unroll
            for (int j = 0; j < 4; ++j) {
                int n0 = wn * 32 + j * 8;
                int l = lane & 15;
                unsigned addr = smem_u32(&sm.ab.B[n0 + (l & 7)][k0 + (l >> 3) * 8]);
                asm volatile("ldmatrix.sync.aligned.m8n8.x2.shared.b16 {%0,%1}, [%2];"
                             : "=r"(bb[j][0]), "=r"(bb[j][1])
                             : "r"(addr));
            }
#pragma unroll
            for (int i = 0; i < 4; ++i)
#pragma unroll
                for (int j = 0; j < 4; ++j) {
                    asm volatile(
                        "mma.sync.aligned.m16n8k16.row.col.f32.bf16.bf16.f32 "
                        "{%0,%1,%2,%3}, {%4,%5,%6,%7}, {%8,%9}, {%0,%1,%2,%3};"
                        : "+f"(acc[i][j][0]), "+f"(acc[i][j][1]),
                          "+f"(acc[i][j][2]), "+f"(acc[i][j][3])
                        : "r"(a[i][0]), "r"(a[i][1]), "r"(a[i][2]), "r"(a[i][3]),
                          "r"(bb[j][0]), "r"(bb[j][1]));
                }
        }
        __syncthreads();
    }

#pragma unroll
    for (int i = 0; i < 4; ++i) {
#pragma unroll
        for (int j = 0; j < 4; ++j) {
            size_t row0 = r0 + wm * 64 + i * 16 + (lane >> 2);
            size_t col  = c0 + wn * 32 + j * 8 + (lane & 3) * 2;
            *(float2*)&out[row0 * Nn + col]       = make_float2(acc[i][j][0], acc[i][j][1]);
            *(float2*)&out[(row0 + 8) * Nn + col] = make_float2(acc[i][j][2], acc[i][j][3]);
        }
    }

    if (bx == by) return;

    for (int chunk = 0; chunk < 4; ++chunk) {
        __syncthreads();
        if (wn == chunk) {
            int rbase = wm * 64 + (lane >> 2);
            int cbase = (lane & 3) * 2;
#pragma unroll
            for (int i = 0; i < 4; ++i)
#pragma unroll
                for (int j = 0; j < 4; ++j) {
                    int r = rbase + i * 16;
                    int c = cbase + j * 8;
                    sm.tr[r][c]         = acc[i][j][0];
                    sm.tr[r][c + 1]     = acc[i][j][1];
                    sm.tr[r + 8][c]     = acc[i][j][2];
                    sm.tr[r + 8][c + 1] = acc[i][j][3];
                }
        }
        __syncthreads();
        int cc0 = tid >> 7;
        int rr  = tid & 127;
#pragma unroll
        for (int it = 0; it < 16; ++it) {
            int cc = cc0 + it * 2;
            out[(size_t)(c0 + chunk * 32 + cc) * Nn + r0 + rr] = sm.tr[rr][cc];
        }
    }
}

// ---------------- launch (only true device pointers cross the boundary) ------
extern "C" void kernel_launch(void* const* d_in, const int* in_sizes, int n_in,
                              void* d_out, int out_size) {
    const float* features = (const float*)d_in[0];
    const float* W0       = (const float*)d_in[1];
    const float* Wm       = (const float*)d_in[2];
    const float* Ws       = (const float*)d_in[3];
    const float* noise    = (const float*)d_in[4];
    const int*   ei       = (const int*)d_in[5];
    float* out = (float*)d_out;

    k_zero<<<(Nn + 255) / 256, 256>>>();
    k_cvt_idx<<<(Ee + 255) / 256, 256>>>(ei);      // conversion + degree (fused)
    k_scan<<<1, 1024>>>();
    k_fill<<<Ee / 256, 256>>>();

    k_gemm_t0<<<dim3(Hh / 64, Nn / 64), 256>>>(features, W0);
    k_agg_h<<<(Nn * 32) / 256, 256>>>();
    k_gemm_ms<<<Nn / 64, 256>>>(Wm, Ws);
    k_agg_msz<<<(Nn * 32) / 256, 256>>>(noise);    // gather + Z + split (fused)
    k_zzt_sym<<<NBLK, 256>>>(out);
}

// round 15
// speedup vs baseline: 1.0145x; 1.0145x over previous
#include <cuda_runtime.h>
#include <cuda_bf16.h>
#include <math.h>

#define Nn   12288
#define Ee   393216
#define INF  256
#define Hh   128
#define DZv  64
#define NB   (Nn / 128)            // 96 tile-rows
#define NBLK (NB * (NB + 1) / 2)   // 4656 triangular tiles

// ---------------- scratch (device globals; NEVER passed as kernel args) -----
__device__ __align__(16) int   g_degi[Nn];
__device__ __align__(16) int   g_off[Nn];
__device__ __align__(16) int   g_pos[Nn];
__device__ __align__(16) int   g_csr[Ee];
__device__ __align__(16) __nv_bfloat16 g_t0h[Nn * Hh];   // bf16 (gathered operand)
__device__ __align__(16) float g_hid[Nn * Hh];           // fp32 accumulated hidden
__device__ __align__(16) __nv_bfloat16 g_t1h[Nn * DZv];  // bf16
__device__ __align__(16) __nv_bfloat16 g_t2h[Nn * DZv];  // bf16
__device__ __align__(16) __nv_bfloat16 g_Za[Nn * 192];   // [hi | lo | hi]
__device__ __align__(16) __nv_bfloat16 g_Zb[Nn * 192];   // [hi | hi | lo]
__device__ __align__(16) int   g_src[Ee];
__device__ __align__(16) int   g_dst[Ee];

__device__ __forceinline__ float node_norm(int node) {
    return rsqrtf(fmaxf((float)g_degi[node], 1.0f));
}

__global__ void k_zero() {
    int i = blockIdx.x * blockDim.x + threadIdx.x;
    if (i < Nn) { g_degi[i] = 0; g_pos[i] = 0; }
}

// ---------------- edge index conversion + degree (fused) ---------------------
__global__ void k_cvt_idx(const int* __restrict__ ei) {
    __shared__ int s_is64;
    if (threadIdx.x == 0) {
        int is64 = 1;
        for (int i = 0; i < 32; ++i)
            if (ei[2 * i + 1] != 0) { is64 = 0; break; }
        s_is64 = is64;
    }
    __syncthreads();
    int e = blockIdx.x * blockDim.x + threadIdx.x;
    if (e >= Ee) return;
    int s, d;
    if (s_is64) {
        s = ei[2 * e];
        d = ei[2 * (Ee + e)];
    } else {
        s = ei[e];
        d = ei[Ee + e];
    }
    g_src[e] = s;
    g_dst[e] = d;
    atomicAdd(&g_degi[d], 1);
}

// ---------------- exclusive prefix scan of g_degi -> g_off -------------------
__global__ void k_scan() {
    const int PER = Nn / 1024;
    int tid = threadIdx.x;
    int lane = tid & 31, wid = tid >> 5;
    int base = tid * PER;
    int loc[PER];
    int sum = 0;
#pragma unroll
    for (int i = 0; i < PER; ++i) { loc[i] = sum; sum += g_degi[base + i]; }
    int v = sum;
#pragma unroll
    for (int off = 1; off < 32; off <<= 1) {
        int nb = __shfl_up_sync(0xffffffffu, v, off);
        if (lane >= off) v += nb;
    }
    __shared__ int ws[32];
    if (lane == 31) ws[wid] = v;
    __syncthreads();
    if (wid == 0) {
        int w = ws[lane];
#pragma unroll
        for (int off = 1; off < 32; off <<= 1) {
            int nb = __shfl_up_sync(0xffffffffu, w, off);
            if (lane >= off) w += nb;
        }
        ws[lane] = w;
    }
    __syncthreads();
    int warp_excl = (wid > 0) ? ws[wid - 1] : 0;
    int thr_excl = warp_excl + v - sum;
#pragma unroll
    for (int i = 0; i < PER; ++i) g_off[base + i] = thr_excl + loc[i];
}

__global__ void k_fill() {
    int e = blockIdx.x * blockDim.x + threadIdx.x;
    if (e >= Ee) return;
    int d = g_dst[e];
    int p = g_off[d] + atomicAdd(&g_pos[d], 1);
    g_csr[p] = g_src[e];
}

// ---------------- t0 = bf16( (features @ W0) * norm ) ------------------------
__global__ void k_gemm_t0(const float* __restrict__ A, const float* __restrict__ B) {
    __shared__ float As[16][68];
    __shared__ float Bs[16][68];
    int tid = threadIdx.x;
    int tx = tid & 15, ty = tid >> 4;
    int r0 = blockIdx.y * 64, c0 = blockIdx.x * 64;

    float acc[4][4] = {};
    for (int k0 = 0; k0 < INF; k0 += 16) {
        {
            int row = tid >> 2;
            int kk  = (tid & 3) * 4;
            float4 v = *(const float4*)&A[(size_t)(r0 + row) * INF + k0 + kk];
            As[kk + 0][row] = v.x; As[kk + 1][row] = v.y;
            As[kk + 2][row] = v.z; As[kk + 3][row] = v.w;
        }
        {
            int krow = tid >> 4;
            int col  = (tid & 15) * 4;
            float4 w = *(const float4*)&B[(size_t)(k0 + krow) * Hh + c0 + col];
            *(float4*)&Bs[krow][col] = w;
        }
        __syncthreads();
#pragma unroll
        for (int k = 0; k < 16; ++k) {
            float4 a = *(float4*)&As[k][ty * 4];
            float4 b = *(float4*)&Bs[k][tx * 4];
            float av[4] = {a.x, a.y, a.z, a.w};
            float bv[4] = {b.x, b.y, b.z, b.w};
#pragma unroll
            for (int i = 0; i < 4; ++i)
#pragma unroll
                for (int j = 0; j < 4; ++j)
                    acc[i][j] += av[i] * bv[j];
        }
        __syncthreads();
    }
#pragma unroll
    for (int i = 0; i < 4; ++i) {
        int r = r0 + ty * 4 + i;
        float n = node_norm(r);
        __nv_bfloat162 p0 = __floats2bfloat162_rn(acc[i][0] * n, acc[i][1] * n);
        __nv_bfloat162 p1 = __floats2bfloat162_rn(acc[i][2] * n, acc[i][3] * n);
        uint2 u;
        u.x = *(unsigned*)&p0;
        u.y = *(unsigned*)&p1;
        *(uint2*)&g_t0h[(size_t)r * Hh + c0 + tx * 4] = u;
    }
}

// ---------------- merged t1/t2 = bf16( norm^2 * (hid @ {Wm,Ws}) ) ------------
__global__ void k_gemm_ms(const float* __restrict__ B1, const float* __restrict__ B2) {
    __shared__ float As[16][68];
    __shared__ float Bs1[16][68];
    __shared__ float Bs2[16][68];
    int tid = threadIdx.x;
    int tx = tid & 15, ty = tid >> 4;
    int r0 = blockIdx.x * 64;

    float acc1[4][4] = {};
    float acc2[4][4] = {};
    for (int k0 = 0; k0 < Hh; k0 += 16) {
        {
            int row = tid >> 2;
            int kk  = (tid & 3) * 4;
            float4 v = *(const float4*)&g_hid[(size_t)(r0 + row) * Hh + k0 + kk];
            As[kk + 0][row] = v.x; As[kk + 1][row] = v.y;
            As[kk + 2][row] = v.z; As[kk + 3][row] = v.w;
        }
        {
            int krow = tid >> 4;
            int col  = (tid & 15) * 4;
            float4 w1 = *(const float4*)&B1[(size_t)(k0 + krow) * DZv + col];
            *(float4*)&Bs1[krow][col] = w1;
            float4 w2 = *(const float4*)&B2[(size_t)(k0 + krow) * DZv + col];
            *(float4*)&Bs2[krow][col] = w2;
        }
        __syncthreads();
#pragma unroll
        for (int k = 0; k < 16; ++k) {
            float4 a = *(float4*)&As[k][ty * 4];
            float av[4] = {a.x, a.y, a.z, a.w};
            float4 b1 = *(float4*)&Bs1[k][tx * 4];
            float bv1[4] = {b1.x, b1.y, b1.z, b1.w};
            float4 b2 = *(float4*)&Bs2[k][tx * 4];
            float bv2[4] = {b2.x, b2.y, b2.z, b2.w};
#pragma unroll
            for (int i = 0; i < 4; ++i)
#pragma unroll
                for (int j = 0; j < 4; ++j) {
                    acc1[i][j] += av[i] * bv1[j];
                    acc2[i][j] += av[i] * bv2[j];
                }
        }
        __syncthreads();
    }
#pragma unroll
    for (int i = 0; i < 4; ++i) {
        int r = r0 + ty * 4 + i;
        float n = node_norm(r);
        float s = n * n;
        __nv_bfloat162 a0 = __floats2bfloat162_rn(acc1[i][0] * s, acc1[i][1] * s);
        __nv_bfloat162 a1 = __floats2bfloat162_rn(acc1[i][2] * s, acc1[i][3] * s);
        uint2 u1; u1.x = *(unsigned*)&a0; u1.y = *(unsigned*)&a1;
        *(uint2*)&g_t1h[(size_t)r * DZv + tx * 4] = u1;
        __nv_bfloat162 b0 = __floats2bfloat162_rn(acc2[i][0] * s, acc2[i][1] * s);
        __nv_bfloat162 b1 = __floats2bfloat162_rn(acc2[i][2] * s, acc2[i][3] * s);
        uint2 u2; u2.x = *(unsigned*)&b0; u2.y = *(unsigned*)&b1;
        *(uint2*)&g_t2h[(size_t)r * DZv + tx * 4] = u2;
    }
}

// ---------------- gather-aggregate hid (warp/node, bf16 loads, fp32 accum) ---
__device__ __forceinline__ void acc_bf16x4(float4& a, uint2 u) {
    float2 f0 = __bfloat1622float2(*reinterpret_cast<__nv_bfloat162*>(&u.x));
    float2 f1 = __bfloat1622float2(*reinterpret_cast<__nv_bfloat162*>(&u.y));
    a.x += f0.x; a.y += f0.y; a.z += f1.x; a.w += f1.y;
}

__global__ void k_agg_h() {
    int gtid = blockIdx.x * blockDim.x + threadIdx.x;
    int node = gtid >> 5;
    int lane = gtid & 31;
    if (node >= Nn) return;
    int beg = g_off[node];
    int end = beg + g_degi[node];
    float4 a0 = make_float4(0.f, 0.f, 0.f, 0.f);
    float4 a1 = make_float4(0.f, 0.f, 0.f, 0.f);
    float4 a2 = make_float4(0.f, 0.f, 0.f, 0.f);
    float4 a3 = make_float4(0.f, 0.f, 0.f, 0.f);
    int i = beg;
    for (; i + 3 < end; i += 4) {
        int s0 = g_csr[i], s1 = g_csr[i + 1], s2 = g_csr[i + 2], s3 = g_csr[i + 3];
        uint2 v0 = ((const uint2*)&g_t0h[(size_t)s0 * Hh])[lane];
        uint2 v1 = ((const uint2*)&g_t0h[(size_t)s1 * Hh])[lane];
        uint2 v2 = ((const uint2*)&g_t0h[(size_t)s2 * Hh])[lane];
        uint2 v3 = ((const uint2*)&g_t0h[(size_t)s3 * Hh])[lane];
        acc_bf16x4(a0, v0);
        acc_bf16x4(a1, v1);
        acc_bf16x4(a2, v2);
        acc_bf16x4(a3, v3);
    }
    for (; i < end; ++i) {
        int s = g_csr[i];
        uint2 v = ((const uint2*)&g_t0h[(size_t)s * Hh])[lane];
        acc_bf16x4(a0, v);
    }
    float4 acc = make_float4(a0.x + a1.x + a2.x + a3.x,
                             a0.y + a1.y + a2.y + a3.y,
                             a0.z + a1.z + a2.z + a3.z,
                             a0.w + a1.w + a2.w + a3.w);
    ((float4*)&g_hid[(size_t)node * Hh])[lane] = acc;
}

// ---------------- fused gather(m,s) + Z + bf16 split (warp/node) -------------
__global__ void k_agg_msz(const float* __restrict__ noise) {
    int gtid = blockIdx.x * blockDim.x + threadIdx.x;
    int node = gtid >> 5;
    int lane = gtid & 31;
    if (node >= Nn) return;
    int beg = g_off[node];
    int end = beg + g_degi[node];
    const __nv_bfloat16* T = (lane < 16) ? g_t1h : g_t2h;
    int q = lane & 15;

    float4 a0 = make_float4(0.f, 0.f, 0.f, 0.f);
    float4 a1 = make_float4(0.f, 0.f, 0.f, 0.f);
    int i = beg;
    for (; i + 1 < end; i += 2) {
        int s0 = g_csr[i], s1 = g_csr[i + 1];
        uint2 v0 = ((const uint2*)&T[(size_t)s0 * DZv])[q];
        uint2 v1 = ((const uint2*)&T[(size_t)s1 * DZv])[q];
        acc_bf16x4(a0, v0);
        acc_bf16x4(a1, v1);
    }
    for (; i < end; ++i) {
        int s = g_csr[i];
        uint2 v = ((const uint2*)&T[(size_t)s * DZv])[q];
        acc_bf16x4(a0, v);
    }
    float n = node_norm(node);
    float4 sc;
    sc.x = fmaxf((a0.x + a1.x) * n, 0.f);
    sc.y = fmaxf((a0.y + a1.y) * n, 0.f);
    sc.z = fmaxf((a0.z + a1.z) * n, 0.f);
    sc.w = fmaxf((a0.w + a1.w) * n, 0.f);

    float4 other;
    other.x = __shfl_xor_sync(0xffffffffu, sc.x, 16);
    other.y = __shfl_xor_sync(0xffffffffu, sc.y, 16);
    other.z = __shfl_xor_sync(0xffffffffu, sc.z, 16);
    other.w = __shfl_xor_sync(0xffffffffu, sc.w, 16);

    if (lane < 16) {
        float4 m4 = sc, s4 = other;
        float4 nz = ((const float4*)&noise[(size_t)node * DZv])[q];
        float z[4];
        z[0] = nz.x * expf(s4.x) + m4.x;
        z[1] = nz.y * expf(s4.y) + m4.y;
        z[2] = nz.z * expf(s4.z) + m4.z;
        z[3] = nz.w * expf(s4.w) + m4.w;
        __nv_bfloat16 hi[4], lo[4];
#pragma unroll
        for (int t = 0; t < 4; ++t) {
            hi[t] = __float2bfloat16(z[t]);
            lo[t] = __float2bfloat16(z[t] - __bfloat162float(hi[t]));
        }
        __nv_bfloat162 h01, h23, l01, l23;
        h01.x = hi[0]; h01.y = hi[1]; h23.x = hi[2]; h23.y = hi[3];
        l01.x = lo[0]; l01.y = lo[1]; l23.x = lo[2]; l23.y = lo[3];
        size_t base2 = (size_t)node * 96 + q * 2;
        __nv_bfloat162* Za2 = (__nv_bfloat162*)g_Za;
        __nv_bfloat162* Zb2 = (__nv_bfloat162*)g_Zb;
        Za2[base2 + 0]  = h01; Za2[base2 + 1]  = h23;
        Za2[base2 + 32] = l01; Za2[base2 + 33] = l23;
        Za2[base2 + 64] = h01; Za2[base2 + 65] = h23;
        Zb2[base2 + 0]  = h01; Zb2[base2 + 1]  = h23;
        Zb2[base2 + 32] = h01; Zb2[base2 + 33] = h23;
        Zb2[base2 + 64] = l01; Zb2[base2 + 65] = l23;
    }
}

// ---------------- symmetric ZZ^T: triangular tiles + smem transpose ----------
#define ZPAD 8
#define ZLD  (64 + ZPAD)

union ZSmem {
    struct { __nv_bfloat16 A[128][ZLD]; __nv_bfloat16 B[128][ZLD]; } ab;
    float tr[128][33];
};

__device__ __forceinline__ unsigned smem_u32(const void* p) {
    return (unsigned)__cvta_generic_to_shared(p);
}

__global__ void __launch_bounds__(256, 2) k_zzt_sym(float* __restrict__ out) {
    __shared__ __align__(16) ZSmem sm;

    int tid  = threadIdx.x;
    int lane = tid & 31;
    int w    = tid >> 5;
    int wm   = w & 1;
    int wn   = w >> 1;

    int b = blockIdx.x;
    int by = (int)((sqrtf(8.0f * (float)b + 1.0f) - 1.0f) * 0.5f);
    while ((by + 1) * (by + 2) / 2 <= b) ++by;
    while (by * (by + 1) / 2 > b) --by;
    int bx = b - by * (by + 1) / 2;
    int r0 = by * 128;
    int c0 = bx * 128;

    float acc[4][4][4];
#pragma unroll
    for (int i = 0; i < 4; ++i)
#pragma unroll
        for (int j = 0; j < 4; ++j)
#pragma unroll
            for (int q = 0; q < 4; ++q) acc[i][j][q] = 0.f;

    for (int kc = 0; kc < 3; ++kc) {
#pragma unroll
        for (int it = 0; it < 4; ++it) {
            int quad = tid + it * 256;
            int row = quad >> 3;
            int q   = quad & 7;
            const uint4* ga = (const uint4*)&g_Za[(size_t)(r0 + row) * 192 + kc * 64];
            *(uint4*)&sm.ab.A[row][q * 8] = ga[q];
            const uint4* gb = (const uint4*)&g_Zb[(size_t)(c0 + row) * 192 + kc * 64];
            *(uint4*)&sm.ab.B[row][q * 8] = gb[q];
        }
        __syncthreads();

#pragma unroll
        for (int ks = 0; ks < 4; ++ks) {
            int k0 = ks * 16;
            unsigned a[4][4];
#pragma unroll
            for (int i = 0; i < 4; ++i) {
                int m0 = wm * 64 + i * 16;
                unsigned addr = smem_u32(&sm.ab.A[m0 + (lane & 15)][k0 + (lane >> 4) * 8]);
                asm volatile("ldmatrix.sync.aligned.m8n8.x4.shared.b16 {%0,%1,%2,%3}, [%4];"
                             : "=r"(a[i][0]), "=r"(a[i][1]), "=r"(a[i][2]), "=r"(a[i][3])
                             : "r"(addr));
            }
            unsigned bb[4][2];
#pragma unroll
            for (int j = 0; j < 4; ++j) {
                int n0 = wn * 32 + j * 8;
                int l = lane & 15;
                unsigned addr = smem_u32(&sm.ab.B[n0 + (l & 7)][k0 + (l >> 3) * 8]);
                asm volatile("ldmatrix.sync.aligned.m8n8.x2.shared.b16 {%0,%1}, [%2];"
                             : "=r"(bb[j][0]), "=r"(bb[j][1])
                             : "r"(addr));
            }
#pragma unroll
            for (int i = 0; i < 4; ++i)
#pragma unroll
                for (int j = 0; j < 4; ++j) {
                    asm volatile(
                        "mma.sync.aligned.m16n8k16.row.col.f32.bf16.bf16.f32 "
                        "{%0,%1,%2,%3}, {%4,%5,%6,%7}, {%8,%9}, {%0,%1,%2,%3};"
                        : "+f"(acc[i][j][0]), "+f"(acc[i][j][1]),
                          "+f"(acc[i][j][2]), "+f"(acc[i][j][3])
                        : "r"(a[i][0]), "r"(a[i][1]), "r"(a[i][2]), "r"(a[i][3]),
                          "r"(bb[j][0]), "r"(bb[j][1]));
                }
        }
        __syncthreads();
    }

#pragma unroll
    for (int i = 0; i < 4; ++i) {
#pragma unroll
        for (int j = 0; j < 4; ++j) {
            size_t row0 = r0 + wm * 64 + i * 16 + (lane >> 2);
            size_t col  = c0 + wn * 32 + j * 8 + (lane & 3) * 2;
            *(float2*)&out[row0 * Nn + col]       = make_float2(acc[i][j][0], acc[i][j][1]);
            *(float2*)&out[(row0 + 8) * Nn + col] = make_float2(acc[i][j][2], acc[i][j][3]);
        }
    }

    if (bx == by) return;

    for (int chunk = 0; chunk < 4; ++chunk) {
        __syncthreads();
        if (wn == chunk) {
            int rbase = wm * 64 + (lane >> 2);
            int cbase = (lane & 3) * 2;
#pragma unroll
            for (int i = 0; i < 4; ++i)
#pragma unroll
                for (int j = 0; j < 4; ++j) {
                    int r = rbase + i * 16;
                    int c = cbase + j * 8;
                    sm.tr[r][c]         = acc[i][j][0];
                    sm.tr[r][c + 1]     = acc[i][j][1];
                    sm.tr[r + 8][c]     = acc[i][j][2];
                    sm.tr[r + 8][c + 1] = acc[i][j][3];
                }
        }
        __syncthreads();
        int cc0 = tid >> 7;
        int rr  = tid & 127;
#pragma unroll
        for (int it = 0; it < 16; ++it) {
            int cc = cc0 + it * 2;
            out[(size_t)(c0 + chunk * 32 + cc) * Nn + r0 + rr] = sm.tr[rr][cc];
        }
    }
}

// ---------------- launch (only true device pointers cross the boundary) ------
extern "C" void kernel_launch(void* const* d_in, const int* in_sizes, int n_in,
                              void* d_out, int out_size) {
    const float* features = (const float*)d_in[0];
    const float* W0       = (const float*)d_in[1];
    const float* Wm       = (const float*)d_in[2];
    const float* Ws       = (const float*)d_in[3];
    const float* noise    = (const float*)d_in[4];
    const int*   ei       = (const int*)d_in[5];
    float* out = (float*)d_out;

    k_zero<<<(Nn + 255) / 256, 256>>>();
    k_cvt_idx<<<(Ee + 255) / 256, 256>>>(ei);
    k_scan<<<1, 1024>>>();
    k_fill<<<Ee / 256, 256>>>();

    k_gemm_t0<<<dim3(Hh / 64, Nn / 64), 256>>>(features, W0);
    k_agg_h<<<(Nn * 32) / 256, 256>>>();
    k_gemm_ms<<<Nn / 64, 256>>>(Wm, Ws);
    k_agg_msz<<<(Nn * 32) / 256, 256>>>(noise);
    k_zzt_sym<<<NBLK, 256>>>(out);
}

// round 16
// speedup vs baseline: 1.0299x; 1.0152x over previous
#include <cuda_runtime.h>
#include <cuda_bf16.h>
#include <math.h>

#define Nn   12288
#define Ee   393216
#define INF  256
#define Hh   128
#define DZv  64
#define NB   (Nn / 128)            // 96 tile-rows
#define NBLK (NB * (NB + 1) / 2)   // 4656 triangular tiles
#define KF   768                   // split-K for features GEMM (3 x 256)

// ---------------- scratch (device globals; NEVER passed as kernel args) -----
__device__ __align__(16) int   g_degi[Nn];
__device__ __align__(16) int   g_off[Nn];
__device__ __align__(16) int   g_pos[Nn];
__device__ __align__(16) int   g_csr[Ee];
__device__ __align__(16) __nv_bfloat16 g_Fa[Nn * KF];     // [hi(F) | lo(F) | hi(F)]
__device__ __align__(16) __nv_bfloat16 g_W0t[Hh * KF];    // row n: [hi(W0[:,n]) | hi | lo]
__device__ __align__(16) __nv_bfloat16 g_t0h[Nn * Hh];    // bf16 t0
__device__ __align__(16) float g_hid[Nn * Hh];            // fp32 hidden
__device__ __align__(16) __nv_bfloat16 g_t1h[Nn * DZv];
__device__ __align__(16) __nv_bfloat16 g_t2h[Nn * DZv];
__device__ __align__(16) __nv_bfloat16 g_Za[Nn * 192];    // [hi | lo | hi]
__device__ __align__(16) __nv_bfloat16 g_Zb[Nn * 192];    // [hi | hi | lo]
__device__ __align__(16) int   g_src[Ee];
__device__ __align__(16) int   g_dst[Ee];

__device__ __forceinline__ float node_norm(int node) {
    return rsqrtf(fmaxf((float)g_degi[node], 1.0f));
}

__global__ void k_zero() {
    int i = blockIdx.x * blockDim.x + threadIdx.x;
    if (i < Nn) { g_degi[i] = 0; g_pos[i] = 0; }
}

// ---------------- edge index conversion + degree (fused) ---------------------
__global__ void k_cvt_idx(const int* __restrict__ ei) {
    __shared__ int s_is64;
    if (threadIdx.x == 0) {
        int is64 = 1;
        for (int i = 0; i < 32; ++i)
            if (ei[2 * i + 1] != 0) { is64 = 0; break; }
        s_is64 = is64;
    }
    __syncthreads();
    int e = blockIdx.x * blockDim.x + threadIdx.x;
    if (e >= Ee) return;
    int s, d;
    if (s_is64) {
        s = ei[2 * e];
        d = ei[2 * (Ee + e)];
    } else {
        s = ei[e];
        d = ei[Ee + e];
    }
    g_src[e] = s;
    g_dst[e] = d;
    atomicAdd(&g_degi[d], 1);
}

// ---------------- exclusive prefix scan of g_degi -> g_off -------------------
__global__ void k_scan() {
    const int PER = Nn / 1024;
    int tid = threadIdx.x;
    int lane = tid & 31, wid = tid >> 5;
    int base = tid * PER;
    int loc[PER];
    int sum = 0;
#pragma unroll
    for (int i = 0; i < PER; ++i) { loc[i] = sum; sum += g_degi[base + i]; }
    int v = sum;
#pragma unroll
    for (int off = 1; off < 32; off <<= 1) {
        int nb = __shfl_up_sync(0xffffffffu, v, off);
        if (lane >= off) v += nb;
    }
    __shared__ int ws[32];
    if (lane == 31) ws[wid] = v;
    __syncthreads();
    if (wid == 0) {
        int w = ws[lane];
#pragma unroll
        for (int off = 1; off < 32; off <<= 1) {
            int nb = __shfl_up_sync(0xffffffffu, w, off);
            if (lane >= off) w += nb;
        }
        ws[lane] = w;
    }
    __syncthreads();
    int warp_excl = (wid > 0) ? ws[wid - 1] : 0;
    int thr_excl = warp_excl + v - sum;
#pragma unroll
    for (int i = 0; i < PER; ++i) g_off[base + i] = thr_excl + loc[i];
}

__global__ void k_fill() {
    int e = blockIdx.x * blockDim.x + threadIdx.x;
    if (e >= Ee) return;
    int d = g_dst[e];
    int p = g_off[d] + atomicAdd(&g_pos[d], 1);
    g_csr[p] = g_src[e];
}

// ---------------- split features -> Fa [hi | lo | hi]  -----------------------
__global__ void k_split_f(const float* __restrict__ F) {
    int idx = blockIdx.x * blockDim.x + threadIdx.x;   // one per 4 fp32
    if (idx >= Nn * INF / 4) return;
    int r = idx >> 6;            // / (256/4)
    int c = (idx & 63) * 4;
    float4 v = *(const float4*)&F[(size_t)r * INF + c];
    float f[4] = {v.x, v.y, v.z, v.w};
    __nv_bfloat16 hi[4], lo[4];
#pragma unroll
    for (int t = 0; t < 4; ++t) {
        hi[t] = __float2bfloat16(f[t]);
        lo[t] = __float2bfloat16(f[t] - __bfloat162float(hi[t]));
    }
    __nv_bfloat162 h01, h23, l01, l23;
    h01.x = hi[0]; h01.y = hi[1]; h23.x = hi[2]; h23.y = hi[3];
    l01.x = lo[0]; l01.y = lo[1]; l23.x = lo[2]; l23.y = lo[3];
    __nv_bfloat162* Fa2 = (__nv_bfloat162*)g_Fa;
    size_t base2 = (size_t)r * (KF / 2) + c / 2;
    Fa2[base2 + 0]   = h01; Fa2[base2 + 1]   = h23;          // hi chunk
    Fa2[base2 + 128] = l01; Fa2[base2 + 129] = l23;          // lo chunk (+256 bf16)
    Fa2[base2 + 256] = h01; Fa2[base2 + 257] = h23;          // hi chunk (+512 bf16)
}

// ---------------- split W0 -> W0t (transposed, [hi | hi | lo] per n-row) -----
__global__ void k_split_w0(const float* __restrict__ W0) {
    int idx = blockIdx.x * blockDim.x + threadIdx.x;   // 256*128 elements
    if (idx >= INF * Hh) return;
    int n = idx & 127;
    int k = idx >> 7;
    float w = W0[(size_t)k * Hh + n];
    __nv_bfloat16 hi = __float2bfloat16(w);
    __nv_bfloat16 lo = __float2bfloat16(w - __bfloat162float(hi));
    size_t base = (size_t)n * KF + k;
    g_W0t[base]       = hi;
    g_W0t[base + 256] = hi;
    g_W0t[base + 512] = lo;
}

// ---------------- shared tensor-core tile helpers ----------------------------
#define ZPAD 8
#define ZLD  (64 + ZPAD)

union ZSmem {
    struct { __nv_bfloat16 A[128][ZLD]; __nv_bfloat16 B[128][ZLD]; } ab;
    float tr[128][33];
};

__device__ __forceinline__ unsigned smem_u32(const void* p) {
    return (unsigned)__cvta_generic_to_shared(p);
}

// ---------------- t0h = bf16( (F @ W0) * norm ) via TC (K=768 split) ---------
__global__ void __launch_bounds__(256, 2) k_gemm_t0_tc() {
    __shared__ __align__(16) ZSmem sm;

    int tid  = threadIdx.x;
    int lane = tid & 31;
    int w    = tid >> 5;
    int wm   = w & 1;
    int wn   = w >> 1;
    int r0 = blockIdx.x * 128;

    float acc[4][4][4];
#pragma unroll
    for (int i = 0; i < 4; ++i)
#pragma unroll
        for (int j = 0; j < 4; ++j)
#pragma unroll
            for (int q = 0; q < 4; ++q) acc[i][j][q] = 0.f;

    for (int kc = 0; kc < KF / 64; ++kc) {      // 12 chunks of 64
#pragma unroll
        for (int it = 0; it < 4; ++it) {
            int quad = tid + it * 256;
            int row = quad >> 3;
            int q   = quad & 7;
            const uint4* ga = (const uint4*)&g_Fa[(size_t)(r0 + row) * KF + kc * 64];
            *(uint4*)&sm.ab.A[row][q * 8] = ga[q];
            const uint4* gb = (const uint4*)&g_W0t[(size_t)row * KF + kc * 64];
            *(uint4*)&sm.ab.B[row][q * 8] = gb[q];
        }
        __syncthreads();

#pragma unroll
        for (int ks = 0; ks < 4; ++ks) {
            int k0 = ks * 16;
            unsigned a[4][4];
#pragma unroll
            for (int i = 0; i < 4; ++i) {
                int m0 = wm * 64 + i * 16;
                unsigned addr = smem_u32(&sm.ab.A[m0 + (lane & 15)][k0 + (lane >> 4) * 8]);
                asm volatile("ldmatrix.sync.aligned.m8n8.x4.shared.b16 {%0,%1,%2,%3}, [%4];"
                             : "=r"(a[i][0]), "=r"(a[i][1]), "=r"(a[i][2]), "=r"(a[i][3])
                             : "r"(addr));
            }
            unsigned bb[4][2];
#pragma unroll
            for (int j = 0; j < 4; ++j) {
                int n0 = wn * 32 + j * 8;
                int l = lane & 15;
                unsigned addr = smem_u32(&sm.ab.B[n0 + (l & 7)][k0 + (l >> 3) * 8]);
                asm volatile("ldmatrix.sync.aligned.m8n8.x2.shared.b16 {%0,%1}, [%2];"
                             : "=r"(bb[j][0]), "=r"(bb[j][1])
                             : "r"(addr));
            }
#pragma unroll
            for (int i = 0; i < 4; ++i)
#pragma unroll
                for (int j = 0; j < 4; ++j) {
                    asm volatile(
                        "mma.sync.aligned.m16n8k16.row.col.f32.bf16.bf16.f32 "
                        "{%0,%1,%2,%3}, {%4,%5,%6,%7}, {%8,%9}, {%0,%1,%2,%3};"
                        : "+f"(acc[i][j][0]), "+f"(acc[i][j][1]),
                          "+f"(acc[i][j][2]), "+f"(acc[i][j][3])
                        : "r"(a[i][0]), "r"(a[i][1]), "r"(a[i][2]), "r"(a[i][3]),
                          "r"(bb[j][0]), "r"(bb[j][1]));
                }
        }
        __syncthreads();
    }

#pragma unroll
    for (int i = 0; i < 4; ++i) {
        int rowA = r0 + wm * 64 + i * 16 + (lane >> 2);
        float n0f = node_norm(rowA);
        float n1f = node_norm(rowA + 8);
#pragma unroll
        for (int j = 0; j < 4; ++j) {
            int col = wn * 32 + j * 8 + (lane & 3) * 2;
            __nv_bfloat162 p0 = __floats2bfloat162_rn(acc[i][j][0] * n0f, acc[i][j][1] * n0f);
            __nv_bfloat162 p1 = __floats2bfloat162_rn(acc[i][j][2] * n1f, acc[i][j][3] * n1f);
            *(__nv_bfloat162*)&g_t0h[(size_t)rowA * Hh + col]       = p0;
            *(__nv_bfloat162*)&g_t0h[(size_t)(rowA + 8) * Hh + col] = p1;
        }
    }
}

// ---------------- merged t1/t2 = bf16( norm^2 * (hid @ {Wm,Ws}) ) ------------
__global__ void k_gemm_ms(const float* __restrict__ B1, const float* __restrict__ B2) {
    __shared__ float As[16][68];
    __shared__ float Bs1[16][68];
    __shared__ float Bs2[16][68];
    int tid = threadIdx.x;
    int tx = tid & 15, ty = tid >> 4;
    int r0 = blockIdx.x * 64;

    float acc1[4][4] = {};
    float acc2[4][4] = {};
    for (int k0 = 0; k0 < Hh; k0 += 16) {
        {
            int row = tid >> 2;
            int kk  = (tid & 3) * 4;
            float4 v = *(const float4*)&g_hid[(size_t)(r0 + row) * Hh + k0 + kk];
            As[kk + 0][row] = v.x; As[kk + 1][row] = v.y;
            As[kk + 2][row] = v.z; As[kk + 3][row] = v.w;
        }
        {
            int krow = tid >> 4;
            int col  = (tid & 15) * 4;
            float4 w1 = *(const float4*)&B1[(size_t)(k0 + krow) * DZv + col];
            *(float4*)&Bs1[krow][col] = w1;
            float4 w2 = *(const float4*)&B2[(size_t)(k0 + krow) * DZv + col];
            *(float4*)&Bs2[krow][col] = w2;
        }
        __syncthreads();
#pragma unroll
        for (int k = 0; k < 16; ++k) {
            float4 a = *(float4*)&As[k][ty * 4];
            float av[4] = {a.x, a.y, a.z, a.w};
            float4 b1 = *(float4*)&Bs1[k][tx * 4];
            float bv1[4] = {b1.x, b1.y, b1.z, b1.w};
            float4 b2 = *(float4*)&Bs2[k][tx * 4];
            float bv2[4] = {b2.x, b2.y, b2.z, b2.w};
#pragma unroll
            for (int i = 0; i < 4; ++i)
#pragma unroll
                for (int j = 0; j < 4; ++j) {
                    acc1[i][j] += av[i] * bv1[j];
                    acc2[i][j] += av[i] * bv2[j];
                }
        }
        __syncthreads();
    }
#pragma unroll
    for (int i = 0; i < 4; ++i) {
        int r = r0 + ty * 4 + i;
        float n = node_norm(r);
        float s = n * n;
        __nv_bfloat162 a0 = __floats2bfloat162_rn(acc1[i][0] * s, acc1[i][1] * s);
        __nv_bfloat162 a1 = __floats2bfloat162_rn(acc1[i][2] * s, acc1[i][3] * s);
        uint2 u1; u1.x = *(unsigned*)&a0; u1.y = *(unsigned*)&a1;
        *(uint2*)&g_t1h[(size_t)r * DZv + tx * 4] = u1;
        __nv_bfloat162 b0 = __floats2bfloat162_rn(acc2[i][0] * s, acc2[i][1] * s);
        __nv_bfloat162 b1 = __floats2bfloat162_rn(acc2[i][2] * s, acc2[i][3] * s);
        uint2 u2; u2.x = *(unsigned*)&b0; u2.y = *(unsigned*)&b1;
        *(uint2*)&g_t2h[(size_t)r * DZv + tx * 4] = u2;
    }
}

// ---------------- gather-aggregate hid (warp/node, bf16 loads, fp32 accum) ---
__device__ __forceinline__ void acc_bf16x4(float4& a, uint2 u) {
    float2 f0 = __bfloat1622float2(*reinterpret_cast<__nv_bfloat162*>(&u.x));
    float2 f1 = __bfloat1622float2(*reinterpret_cast<__nv_bfloat162*>(&u.y));
    a.x += f0.x; a.y += f0.y; a.z += f1.x; a.w += f1.y;
}

__global__ void k_agg_h() {
    int gtid = blockIdx.x * blockDim.x + threadIdx.x;
    int node = gtid >> 5;
    int lane = gtid & 31;
    if (node >= Nn) return;
    int beg = g_off[node];
    int end = beg + g_degi[node];
    float4 a0 = make_float4(0.f, 0.f, 0.f, 0.f);
    float4 a1 = make_float4(0.f, 0.f, 0.f, 0.f);
    float4 a2 = make_float4(0.f, 0.f, 0.f, 0.f);
    float4 a3 = make_float4(0.f, 0.f, 0.f, 0.f);
    int i = beg;
    for (; i + 3 < end; i += 4) {
        int s0 = g_csr[i], s1 = g_csr[i + 1], s2 = g_csr[i + 2], s3 = g_csr[i + 3];
        uint2 v0 = ((const uint2*)&g_t0h[(size_t)s0 * Hh])[lane];
        uint2 v1 = ((const uint2*)&g_t0h[(size_t)s1 * Hh])[lane];
        uint2 v2 = ((const uint2*)&g_t0h[(size_t)s2 * Hh])[lane];
        uint2 v3 = ((const uint2*)&g_t0h[(size_t)s3 * Hh])[lane];
        acc_bf16x4(a0, v0);
        acc_bf16x4(a1, v1);
        acc_bf16x4(a2, v2);
        acc_bf16x4(a3, v3);
    }
    for (; i < end; ++i) {
        int s = g_csr[i];
        uint2 v = ((const uint2*)&g_t0h[(size_t)s * Hh])[lane];
        acc_bf16x4(a0, v);
    }
    float4 acc = make_float4(a0.x + a1.x + a2.x + a3.x,
                             a0.y + a1.y + a2.y + a3.y,
                             a0.z + a1.z + a2.z + a3.z,
                             a0.w + a1.w + a2.w + a3.w);
    ((float4*)&g_hid[(size_t)node * Hh])[lane] = acc;
}

// ---------------- fused gather(m,s) + Z + bf16 split (warp/node) -------------
__global__ void k_agg_msz(const float* __restrict__ noise) {
    int gtid = blockIdx.x * blockDim.x + threadIdx.x;
    int node = gtid >> 5;
    int lane = gtid & 31;
    if (node >= Nn) return;
    int beg = g_off[node];
    int end = beg + g_degi[node];
    const __nv_bfloat16* T = (lane < 16) ? g_t1h : g_t2h;
    int q = lane & 15;

    float4 a0 = make_float4(0.f, 0.f, 0.f, 0.f);
    float4 a1 = make_float4(0.f, 0.f, 0.f, 0.f);
    int i = beg;
    for (; i + 1 < end; i += 2) {
        int s0 = g_csr[i], s1 = g_csr[i + 1];
        uint2 v0 = ((const uint2*)&T[(size_t)s0 * DZv])[q];
        uint2 v1 = ((const uint2*)&T[(size_t)s1 * DZv])[q];
        acc_bf16x4(a0, v0);
        acc_bf16x4(a1, v1);
    }
    for (; i < end; ++i) {
        int s = g_csr[i];
        uint2 v = ((const uint2*)&T[(size_t)s * DZv])[q];
        acc_bf16x4(a0, v);
    }
    float n = node_norm(node);
    float4 sc;
    sc.x = fmaxf((a0.x + a1.x) * n, 0.f);
    sc.y = fmaxf((a0.y + a1.y) * n, 0.f);
    sc.z = fmaxf((a0.z + a1.z) * n, 0.f);
    sc.w = fmaxf((a0.w + a1.w) * n, 0.f);

    float4 other;
    other.x = __shfl_xor_sync(0xffffffffu, sc.x, 16);
    other.y = __shfl_xor_sync(0xffffffffu, sc.y, 16);
    other.z = __shfl_xor_sync(0xffffffffu, sc.z, 16);
    other.w = __shfl_xor_sync(0xffffffffu, sc.w, 16);

    if (lane < 16) {
        float4 m4 = sc, s4 = other;
        float4 nz = ((const float4*)&noise[(size_t)node * DZv])[q];
        float z[4];
        z[0] = nz.x * expf(s4.x) + m4.x;
        z[1] = nz.y * expf(s4.y) + m4.y;
        z[2] = nz.z * expf(s4.z) + m4.z;
        z[3] = nz.w * expf(s4.w) + m4.w;
        __nv_bfloat16 hi[4], lo[4];
#pragma unroll
        for (int t = 0; t < 4; ++t) {
            hi[t] = __float2bfloat16(z[t]);
            lo[t] = __float2bfloat16(z[t] - __bfloat162float(hi[t]));
        }
        __nv_bfloat162 h01, h23, l01, l23;
        h01.x = hi[0]; h01.y = hi[1]; h23.x = hi[2]; h23.y = hi[3];
        l01.x = lo[0]; l01.y = lo[1]; l23.x = lo[2]; l23.y = lo[3];
        size_t base2 = (size_t)node * 96 + q * 2;
        __nv_bfloat162* Za2 = (__nv_bfloat162*)g_Za;
        __nv_bfloat162* Zb2 = (__nv_bfloat162*)g_Zb;
        Za2[base2 + 0]  = h01; Za2[base2 + 1]  = h23;
        Za2[base2 + 32] = l01; Za2[base2 + 33] = l23;
        Za2[base2 + 64] = h01; Za2[base2 + 65] = h23;
        Zb2[base2 + 0]  = h01; Zb2[base2 + 1]  = h23;
        Zb2[base2 + 32] = h01; Zb2[base2 + 33] = h23;
        Zb2[base2 + 64] = l01; Zb2[base2 + 65] = l23;
    }
}

// ---------------- symmetric ZZ^T: triangular tiles + smem transpose ----------
__global__ void __launch_bounds__(256, 2) k_zzt_sym(float* __restrict__ out) {
    __shared__ __align__(16) ZSmem sm;

    int tid  = threadIdx.x;
    int lane = tid & 31;
    int w    = tid >> 5;
    int wm   = w & 1;
    int wn   = w >> 1;

    int b = blockIdx.x;
    int by = (int)((sqrtf(8.0f * (float)b + 1.0f) - 1.0f) * 0.5f);
    while ((by + 1) * (by + 2) / 2 <= b) ++by;
    while (by * (by + 1) / 2 > b) --by;
    int bx = b - by * (by + 1) / 2;
    int r0 = by * 128;
    int c0 = bx * 128;

    float acc[4][4][4];
#pragma unroll
    for (int i = 0; i < 4; ++i)
#pragma unroll
        for (int j = 0; j < 4; ++j)
#pragma unroll
            for (int q = 0; q < 4; ++q) acc[i][j][q] = 0.f;

    for (int kc = 0; kc < 3; ++kc) {
#pragma unroll
        for (int it = 0; it < 4; ++it) {
            int quad = tid + it * 256;
            int row = quad >> 3;
            int q   = quad & 7;
            const uint4* ga = (const uint4*)&g_Za[(size_t)(r0 + row) * 192 + kc * 64];
            *(uint4*)&sm.ab.A[row][q * 8] = ga[q];
            const uint4* gb = (const uint4*)&g_Zb[(size_t)(c0 + row) * 192 + kc * 64];
            *(uint4*)&sm.ab.B[row][q * 8] = gb[q];
        }
        __syncthreads();

#pragma unroll
        for (int ks = 0; ks < 4; ++ks) {
            int k0 = ks * 16;
            unsigned a[4][4];
#pragma unroll
            for (int i = 0; i < 4; ++i) {
                int m0 = wm * 64 + i * 16;
                unsigned addr = smem_u32(&sm.ab.A[m0 + (lane & 15)][k0 + (lane >> 4) * 8]);
                asm volatile("ldmatrix.sync.aligned.m8n8.x4.shared.b16 {%0,%1,%2,%3}, [%4];"
                             : "=r"(a[i][0]), "=r"(a[i][1]), "=r"(a[i][2]), "=r"(a[i][3])
                             : "r"(addr));
            }
            unsigned bb[4][2];
#pragma unroll
            for (int j = 0; j < 4; ++j) {
                int n0 = wn * 32 + j * 8;
                int l = lane & 15;
                unsigned addr = smem_u32(&sm.ab.B[n0 + (l & 7)][k0 + (l >> 3) * 8]);
                asm volatile("ldmatrix.sync.aligned.m8n8.x2.shared.b16 {%0,%1}, [%2];"
                             : "=r"(bb[j][0]), "=r"(bb[j][1])
                             : "r"(addr));
            }
#pragma unroll
            for (int i = 0; i < 4; ++i)
#pragma unroll
                for (int j = 0; j < 4; ++j) {
                    asm volatile(
                        "mma.sync.aligned.m16n8k16.row.col.f32.bf16.bf16.f32 "
                        "{%0,%1,%2,%3}, {%4,%5,%6,%7}, {%8,%9}, {%0,%1,%2,%3};"
                        : "+f"(acc[i][j][0]), "+f"(acc[i][j][1]),
                          "+f"(acc[i][j][2]), "+f"(acc[i][j][3])
                        : "r"(a[i][0]), "r"(a[i][1]), "r"(a[i][2]), "r"(a[i][3]),
                          "r"(bb[j][0]), "r"(bb[j][1]));
                }
        }
        __syncthreads();
    }

#pragma unroll
    for (int i = 0; i < 4; ++i) {
#pragma unroll
        for (int j = 0; j < 4; ++j) {
            size_t row0 = r0 + wm * 64 + i * 16 + (lane >> 2);
            size_t col  = c0 + wn * 32 + j * 8 + (lane & 3) * 2;
            *(float2*)&out[row0 * Nn + col]       = make_float2(acc[i][j][0], acc[i][j][1]);
            *(float2*)&out[(row0 + 8) * Nn + col] = make_float2(acc[i][j][2], acc[i][j][3]);
        }
    }

    if (bx == by) return;

    for (int chunk = 0; chunk < 4; ++chunk) {
        __syncthreads();
        if (wn == chunk) {
            int rbase = wm * 64 + (lane >> 2);
            int cbase = (lane & 3) * 2;
#pragma unroll
            for (int i = 0; i < 4; ++i)
#pragma unroll
                for (int j = 0; j < 4; ++j) {
                    int r = rbase + i * 16;
                    int c = cbase + j * 8;
                    sm.tr[r][c]         = acc[i][j][0];
                    sm.tr[r][c + 1]     = acc[i][j][1];
                    sm.tr[r + 8][c]     = acc[i][j][2];
                    sm.tr[r + 8][c + 1] = acc[i][j][3];
                }
        }
        __syncthreads();
        int cc0 = tid >> 7;
        int rr  = tid & 127;
#pragma unroll
        for (int it = 0; it < 16; ++it) {
            int cc = cc0 + it * 2;
            out[(size_t)(c0 + chunk * 32 + cc) * Nn + r0 + rr] = sm.tr[rr][cc];
        }
    }
}

// ---------------- launch (only true device pointers cross the boundary) ------
extern "C" void kernel_launch(void* const* d_in, const int* in_sizes, int n_in,
                              void* d_out, int out_size) {
    const float* features = (const float*)d_in[0];
    const float* W0       = (const float*)d_in[1];
    const float* Wm       = (const float*)d_in[2];
    const float* Ws       = (const float*)d_in[3];
    const float* noise    = (const float*)d_in[4];
    const int*   ei       = (const int*)d_in[5];
    float* out = (float*)d_out;

    k_zero<<<(Nn + 255) / 256, 256>>>();
    k_cvt_idx<<<(Ee + 255) / 256, 256>>>(ei);
    k_scan<<<1, 1024>>>();
    k_fill<<<Ee / 256, 256>>>();

    // feature / weight hi-lo split for TC GEMM
    k_split_f<<<(Nn * INF / 4 + 255) / 256, 256>>>(features);
    k_split_w0<<<(INF * Hh + 255) / 256, 256>>>(W0);

    // t0h = bf16((F @ W0) * norm) on tensor cores (K=768)
    k_gemm_t0_tc<<<Nn / 128, 256>>>();

    k_agg_h<<<(Nn * 32) / 256, 256>>>();
    k_gemm_ms<<<Nn / 64, 256>>>(Wm, Ws);
    k_agg_msz<<<(Nn * 32) / 256, 256>>>(noise);
    k_zzt_sym<<<NBLK, 256>>>(out);
}